// round 1
// baseline (speedup 1.0000x reference)
#include <cuda_runtime.h>
#include <cuda_bf16.h>
#include <math.h>

// Problem constants
#define Bc 64
#define Tt 197
#define Dd 768
#define Hh 12
#define DKk 64
#define Mrows (Bc * Tt)   // 12608

// Scratch buffers ([B,H,T,DK] for q/k/v, [B,T,D] for ctx)
__device__ float g_q[Bc * Hh * Tt * DKk];
__device__ float g_k[Bc * Hh * Tt * DKk];
__device__ float g_v[Bc * Hh * Tt * DKk];
__device__ float g_ctx[Bc * Tt * Dd];

// ---------------------------------------------------------------------------
// Tiled SGEMM: out = A[M,768] @ W[768,768] + bias
// mode 0: write head-split layout [B,H,T,DK]; mode 1: row-major [M,768]
// 128x128 tile, 8x8 per-thread microtile, KT=8
// ---------------------------------------------------------------------------
__global__ void __launch_bounds__(256) sgemm_kernel(
    const float* __restrict__ A, const float* __restrict__ W,
    const float* __restrict__ bias, float* __restrict__ out, int mode)
{
    __shared__ float As[8][128];
    __shared__ float Ws[8][128];

    const int tx = threadIdx.x & 15;
    const int ty = threadIdx.x >> 4;
    const int m0 = blockIdx.y * 128;
    const int n0 = blockIdx.x * 128;

    float c[8][8];
#pragma unroll
    for (int i = 0; i < 8; i++)
#pragma unroll
        for (int j = 0; j < 8; j++) c[i][j] = 0.f;

    for (int k0 = 0; k0 < Dd; k0 += 8) {
        // A tile: 128 rows x 8 k-cols -> As[k][row]
#pragma unroll
        for (int e = threadIdx.x; e < 128 * 8; e += 256) {
            int r = e >> 3, kc = e & 7;
            int gm = m0 + r;
            As[kc][r] = (gm < Mrows) ? A[(size_t)gm * Dd + k0 + kc] : 0.f;
        }
        // W tile: 8 k-rows x 128 n-cols -> Ws[k][col] (coalesced)
#pragma unroll
        for (int e = threadIdx.x; e < 8 * 128; e += 256) {
            int r = e >> 7, cc = e & 127;
            Ws[r][cc] = W[(size_t)(k0 + r) * Dd + n0 + cc];
        }
        __syncthreads();

#pragma unroll
        for (int kk = 0; kk < 8; kk++) {
            float a[8], b[8];
#pragma unroll
            for (int i = 0; i < 4; i++) {
                a[i]     = As[kk][ty * 4 + i];
                a[4 + i] = As[kk][64 + ty * 4 + i];
                b[i]     = Ws[kk][tx * 4 + i];
                b[4 + i] = Ws[kk][64 + tx * 4 + i];
            }
#pragma unroll
            for (int i = 0; i < 8; i++)
#pragma unroll
                for (int j = 0; j < 8; j++) c[i][j] += a[i] * b[j];
        }
        __syncthreads();
    }

    // epilogue
#pragma unroll
    for (int i = 0; i < 8; i++) {
        int r = m0 + ((i < 4) ? (ty * 4 + i) : (64 + ty * 4 + (i - 4)));
        if (r >= Mrows) continue;
        int bi = r / Tt;
        int t  = r - bi * Tt;
#pragma unroll
        for (int j = 0; j < 8; j++) {
            int cidx = n0 + ((j < 4) ? (tx * 4 + j) : (64 + tx * 4 + (j - 4)));
            float v = c[i][j] + bias[cidx];
            if (mode == 0) {
                int h = cidx >> 6, dk = cidx & 63;
                out[(((size_t)(bi * Hh + h)) * Tt + t) * DKk + dk] = v;
            } else {
                out[(size_t)r * Dd + cidx] = v;
            }
        }
    }
}

// ---------------------------------------------------------------------------
// Attention core: per (b,h) CTA. K/V tile in smem (row-padded to 65 floats),
// warp-per-query-row. scores -> floor(s/8) -> softmax -> @V.
// ctx written as [B,T,D].
// ---------------------------------------------------------------------------
#define SROW 65
#define ATTN_SMEM ((2 * Tt * SROW + 8 * 200) * 4)

__global__ void __launch_bounds__(256) attn_kernel(
    const float* __restrict__ Q, const float* __restrict__ K,
    const float* __restrict__ V, float* __restrict__ ctx)
{
    extern __shared__ float sm[];
    float* Ks = sm;                  // Tt * SROW
    float* Vs = sm + Tt * SROW;      // Tt * SROW
    float* Ps = sm + 2 * Tt * SROW;  // 8 warps * 200

    const int tid  = threadIdx.x;
    const int lane = tid & 31;
    const int w    = tid >> 5;
    const int bh   = blockIdx.x;      // 0 .. B*H-1
    const int b    = bh / Hh;
    const int h    = bh - b * Hh;

    const float* Kb = K + (size_t)bh * Tt * DKk;
    const float* Vb = V + (size_t)bh * Tt * DKk;
    const float* Qb = Q + (size_t)bh * Tt * DKk;

    for (int e = tid; e < Tt * DKk; e += 256) {
        int j = e >> 6, d = e & 63;
        Ks[j * SROW + d] = Kb[e];
        Vs[j * SROW + d] = Vb[e];
    }
    __syncthreads();

    float* Pw = Ps + w * 200;

    for (int row = w; row < Tt; row += 8) {
        const float* q = Qb + row * DKk;

        float sc[7];
        float mx = -1e30f;
#pragma unroll
        for (int u = 0; u < 7; u++) {
            int j = lane + u * 32;
            float s = -1e30f;
            if (j < Tt) {
                s = 0.f;
#pragma unroll
                for (int d = 0; d < 64; d++) s += q[d] * Ks[j * SROW + d];
                s = floorf(s * 0.125f);   // floor(scores / sqrt(64))
            }
            sc[u] = s;
            mx = fmaxf(mx, s);
        }
#pragma unroll
        for (int o = 16; o; o >>= 1) mx = fmaxf(mx, __shfl_xor_sync(0xffffffffu, mx, o));

        float sum = 0.f;
#pragma unroll
        for (int u = 0; u < 7; u++) {
            int j = lane + u * 32;
            if (j < Tt) {
                float p = expf(sc[u] - mx);
                Pw[j] = p;
                sum += p;
            }
        }
#pragma unroll
        for (int o = 16; o; o >>= 1) sum += __shfl_xor_sync(0xffffffffu, sum, o);
        float inv = 1.f / sum;
        __syncwarp();

        float acc0 = 0.f, acc1 = 0.f;
        for (int j = 0; j < Tt; j++) {
            float p = Pw[j];
            acc0 += p * Vs[j * SROW + lane];
            acc1 += p * Vs[j * SROW + lane + 32];
        }

        float* o = ctx + ((size_t)(b * Tt + row)) * Dd + h * DKk;
        o[lane]      = acc0 * inv;
        o[lane + 32] = acc1 * inv;
        __syncwarp();   // Pw reused next row iteration
    }
}

// ---------------------------------------------------------------------------
extern "C" void kernel_launch(void* const* d_in, const int* in_sizes, int n_in,
                              void* d_out, int out_size)
{
    const float* x  = (const float*)d_in[0];
    const float* Wq = (const float*)d_in[1];
    const float* bq = (const float*)d_in[2];
    const float* Wk = (const float*)d_in[3];
    const float* bk = (const float*)d_in[4];
    const float* Wv = (const float*)d_in[5];
    const float* bv = (const float*)d_in[6];
    const float* Wo = (const float*)d_in[7];
    const float* bo = (const float*)d_in[8];
    float* out = (float*)d_out;

    float *q, *k, *v, *ctx;
    cudaGetSymbolAddress((void**)&q,   g_q);
    cudaGetSymbolAddress((void**)&k,   g_k);
    cudaGetSymbolAddress((void**)&v,   g_v);
    cudaGetSymbolAddress((void**)&ctx, g_ctx);

    cudaFuncSetAttribute(attn_kernel,
                         cudaFuncAttributeMaxDynamicSharedMemorySize, ATTN_SMEM);

    dim3 gridG(Dd / 128, (Mrows + 127) / 128);   // 6 x 99
    sgemm_kernel<<<gridG, 256>>>(x, Wq, bq, q, 0);
    sgemm_kernel<<<gridG, 256>>>(x, Wk, bk, k, 0);
    sgemm_kernel<<<gridG, 256>>>(x, Wv, bv, v, 0);

    attn_kernel<<<Bc * Hh, 256, ATTN_SMEM>>>(q, k, v, ctx);

    sgemm_kernel<<<gridG, 256>>>(ctx, Wo, bo, out, 1);
}

// round 2
// speedup vs baseline: 1.4615x; 1.4615x over previous
#include <cuda_runtime.h>
#include <cuda_bf16.h>
#include <math.h>

#define Bc 64
#define Tt 197
#define Dd 768
#define Hh 12
#define DKk 64
#define Mrows (Bc * Tt)   // 12608

typedef unsigned long long u64;

__device__ __forceinline__ u64 pk2(float lo, float hi) {
    u64 r; asm("mov.b64 %0,{%1,%2};" : "=l"(r) : "f"(lo), "f"(hi)); return r;
}
__device__ __forceinline__ float2 upk2(u64 v) {
    float2 f; asm("mov.b64 {%0,%1},%2;" : "=f"(f.x), "=f"(f.y) : "l"(v)); return f;
}
__device__ __forceinline__ void ffma2(u64 &c, u64 a, u64 b) {
    asm("fma.rn.f32x2 %0,%1,%2,%0;" : "+l"(c) : "l"(a), "l"(b));
}

// Scratch
__device__ float g_q[Bc * Hh * Tt * DKk];
__device__ float g_k[Bc * Hh * Tt * DKk];
__device__ float g_v[Bc * Hh * Tt * DKk];
__device__ float g_ctx[Bc * Tt * Dd];

// ---------------------------------------------------------------------------
// SGEMM with packed fp32 (fma.rn.f32x2): out = A[M,768] @ W[768,768] + bias
// 128x128 tile, KT=16, 8x8 microtile (4 M-pairs x 8 N), 256 threads.
// mode 0: head-split write [B,H,T,DK]; mode 1: row-major [M,768]
// ---------------------------------------------------------------------------
#define KT 16
__global__ void __launch_bounds__(256) sgemm2_kernel(
    const float* __restrict__ A, const float* __restrict__ W,
    const float* __restrict__ bias, float* __restrict__ out, int mode)
{
    __shared__ float As[KT][128];
    __shared__ float Ws[KT][128];

    const int tid = threadIdx.x;
    const int tx = tid & 15;
    const int ty = tid >> 4;
    const int m0 = blockIdx.y * 128;
    const int n0 = blockIdx.x * 128;

    u64 c2[4][8];
#pragma unroll
    for (int i = 0; i < 4; i++)
#pragma unroll
        for (int j = 0; j < 8; j++) c2[i][j] = 0ull;

    // loader indices
    const int ar = tid >> 1;          // A row 0..127
    const int ah = tid & 1;           // A k-half (8 floats each)
    const int wk = tid >> 5;          // W k-row 0..7 (and +8)
    const int wc = tid & 31;          // W col-chunk

    for (int k0 = 0; k0 < Dd; k0 += KT) {
        // A tile: row ar, k = k0+ah*8 .. +7
        float4 a0 = make_float4(0.f, 0.f, 0.f, 0.f), a1 = a0;
        if (m0 + ar < Mrows) {
            const float* Ap = A + (size_t)(m0 + ar) * Dd + k0 + ah * 8;
            a0 = *(const float4*)Ap;
            a1 = *(const float4*)(Ap + 4);
        }
        // W tile
        const float* Wp = W + (size_t)(k0 + wk) * Dd + n0 + wc * 4;
        float4 w0 = *(const float4*)Wp;
        float4 w1 = *(const float4*)(Wp + 8 * Dd);

        As[ah * 8 + 0][ar] = a0.x; As[ah * 8 + 1][ar] = a0.y;
        As[ah * 8 + 2][ar] = a0.z; As[ah * 8 + 3][ar] = a0.w;
        As[ah * 8 + 4][ar] = a1.x; As[ah * 8 + 5][ar] = a1.y;
        As[ah * 8 + 6][ar] = a1.z; As[ah * 8 + 7][ar] = a1.w;
        *(float4*)&Ws[wk][wc * 4]     = w0;
        *(float4*)&Ws[wk + 8][wc * 4] = w1;
        __syncthreads();

#pragma unroll
        for (int kk = 0; kk < KT; kk++) {
            float4 av0 = *(const float4*)&As[kk][ty * 4];
            float4 av1 = *(const float4*)&As[kk][64 + ty * 4];
            float4 bv0 = *(const float4*)&Ws[kk][tx * 4];
            float4 bv1 = *(const float4*)&Ws[kk][64 + tx * 4];
            u64 ap[4];
            ap[0] = pk2(av0.x, av0.y); ap[1] = pk2(av0.z, av0.w);
            ap[2] = pk2(av1.x, av1.y); ap[3] = pk2(av1.z, av1.w);
            u64 bd[8];
            bd[0] = pk2(bv0.x, bv0.x); bd[1] = pk2(bv0.y, bv0.y);
            bd[2] = pk2(bv0.z, bv0.z); bd[3] = pk2(bv0.w, bv0.w);
            bd[4] = pk2(bv1.x, bv1.x); bd[5] = pk2(bv1.y, bv1.y);
            bd[6] = pk2(bv1.z, bv1.z); bd[7] = pk2(bv1.w, bv1.w);
#pragma unroll
            for (int i = 0; i < 4; i++)
#pragma unroll
                for (int j = 0; j < 8; j++) ffma2(c2[i][j], ap[i], bd[j]);
        }
        __syncthreads();
    }

    // epilogue: pair i covers rows {base, base+1}
#pragma unroll
    for (int i = 0; i < 4; i++) {
        int rbase = m0 + ((i < 2) ? (ty * 4 + i * 2) : (64 + ty * 4 + (i - 2) * 2));
#pragma unroll
        for (int j = 0; j < 8; j++) {
            int cidx = n0 + ((j < 4) ? (tx * 4 + j) : (64 + tx * 4 + (j - 4)));
            float2 f = upk2(c2[i][j]);
            float bia = bias[cidx];
            f.x += bia; f.y += bia;
#pragma unroll
            for (int s = 0; s < 2; s++) {
                int r = rbase + s;
                if (r >= Mrows) continue;
                float v = s ? f.y : f.x;
                if (mode == 0) {
                    int bi = r / Tt, t = r - (r / Tt) * Tt;
                    int h = cidx >> 6, dk = cidx & 63;
                    out[(((size_t)(bi * Hh + h)) * Tt + t) * DKk + dk] = v;
                } else {
                    out[(size_t)r * Dd + cidx] = v;
                }
            }
        }
    }
}

// ---------------------------------------------------------------------------
// Attention core v2: per (b,h) CTA, 512 threads (16 warps), 2 rows per warp.
// K/V in smem, rows padded to 68 floats (conflict-free float4 & float2 access).
// scores -> floor(s/8) -> softmax -> @V, all vectorized + f32x2.
// ---------------------------------------------------------------------------
#define SROW 68
#define ATTN_SMEM ((2 * Tt * SROW + 16 * 400) * 4)

__global__ void __launch_bounds__(512) attn2_kernel(
    const float* __restrict__ Q, const float* __restrict__ K,
    const float* __restrict__ V, float* __restrict__ ctx)
{
    extern __shared__ float sm[];
    float* Ks = sm;
    float* Vs = sm + Tt * SROW;
    float* Ps = sm + 2 * Tt * SROW;

    const int tid  = threadIdx.x;
    const int lane = tid & 31;
    const int w    = tid >> 5;
    const int bh   = blockIdx.x;
    const int b    = bh / Hh;
    const int h    = bh - b * Hh;

    const float* Kb = K + (size_t)bh * Tt * DKk;
    const float* Vb = V + (size_t)bh * Tt * DKk;
    const float* Qb = Q + (size_t)bh * Tt * DKk;

    // fill K/V (float4)
    for (int e = tid; e < Tt * 16; e += 512) {
        int j = e >> 4, c = e & 15;
        *(float4*)&Ks[j * SROW + c * 4] = *(const float4*)&Kb[j * DKk + c * 4];
        *(float4*)&Vs[j * SROW + c * 4] = *(const float4*)&Vb[j * DKk + c * 4];
    }
    __syncthreads();

    float* P0 = Ps + w * 400;
    float* P1 = P0 + 200;

    int jj[7];
#pragma unroll
    for (int u = 0; u < 7; u++) {
        int j = lane + u * 32;
        jj[u] = (j > Tt - 1) ? (Tt - 1) : j;
    }

    for (int r0 = w * 2; r0 < Tt; r0 += 32) {
        int r1 = (r0 + 1 < Tt) ? (r0 + 1) : (Tt - 1);
        const float* q0 = Qb + r0 * DKk;
        const float* q1 = Qb + r1 * DKk;

        u64 acc0[7], acc1[7];
#pragma unroll
        for (int u = 0; u < 7; u++) { acc0[u] = 0ull; acc1[u] = 0ull; }

#pragma unroll
        for (int dc = 0; dc < 8; dc++) {
            float4 qa0 = *(const float4*)(q0 + dc * 8);
            float4 qb0 = *(const float4*)(q0 + dc * 8 + 4);
            float4 qa1 = *(const float4*)(q1 + dc * 8);
            float4 qb1 = *(const float4*)(q1 + dc * 8 + 4);
            u64 qp0[4], qp1[4];
            qp0[0] = pk2(qa0.x, qa0.y); qp0[1] = pk2(qa0.z, qa0.w);
            qp0[2] = pk2(qb0.x, qb0.y); qp0[3] = pk2(qb0.z, qb0.w);
            qp1[0] = pk2(qa1.x, qa1.y); qp1[1] = pk2(qa1.z, qa1.w);
            qp1[2] = pk2(qb1.x, qb1.y); qp1[3] = pk2(qb1.z, qb1.w);
#pragma unroll
            for (int u = 0; u < 7; u++) {
                const float* kr = &Ks[jj[u] * SROW + dc * 8];
                float4 ka = *(const float4*)kr;
                float4 kb = *(const float4*)(kr + 4);
                u64 kp0 = pk2(ka.x, ka.y), kp1 = pk2(ka.z, ka.w);
                u64 kp2 = pk2(kb.x, kb.y), kp3 = pk2(kb.z, kb.w);
                ffma2(acc0[u], qp0[0], kp0); ffma2(acc0[u], qp0[1], kp1);
                ffma2(acc0[u], qp0[2], kp2); ffma2(acc0[u], qp0[3], kp3);
                ffma2(acc1[u], qp1[0], kp0); ffma2(acc1[u], qp1[1], kp1);
                ffma2(acc1[u], qp1[2], kp2); ffma2(acc1[u], qp1[3], kp3);
            }
        }

        // scores + max
        float s0[7], s1[7];
        float mx0 = -1e30f, mx1 = -1e30f;
#pragma unroll
        for (int u = 0; u < 7; u++) {
            float2 f0 = upk2(acc0[u]);
            float2 f1 = upk2(acc1[u]);
            float v0 = floorf((f0.x + f0.y) * 0.125f);
            float v1 = floorf((f1.x + f1.y) * 0.125f);
            bool valid = (lane + u * 32) < Tt;
            s0[u] = valid ? v0 : -1e30f;
            s1[u] = valid ? v1 : -1e30f;
            mx0 = fmaxf(mx0, s0[u]);
            mx1 = fmaxf(mx1, s1[u]);
        }
#pragma unroll
        for (int o = 16; o; o >>= 1) {
            mx0 = fmaxf(mx0, __shfl_xor_sync(0xffffffffu, mx0, o));
            mx1 = fmaxf(mx1, __shfl_xor_sync(0xffffffffu, mx1, o));
        }

        float sum0 = 0.f, sum1 = 0.f;
#pragma unroll
        for (int u = 0; u < 7; u++) {
            int j = lane + u * 32;
            if (j < Tt) {
                float p0 = __expf(s0[u] - mx0);
                float p1 = __expf(s1[u] - mx1);
                P0[j] = p0; P1[j] = p1;
                sum0 += p0; sum1 += p1;
            }
        }
#pragma unroll
        for (int o = 16; o; o >>= 1) {
            sum0 += __shfl_xor_sync(0xffffffffu, sum0, o);
            sum1 += __shfl_xor_sync(0xffffffffu, sum1, o);
        }
        float inv0 = 1.f / sum0, inv1 = 1.f / sum1;
        __syncwarp();

        // AV: lane owns d-pair (2*lane, 2*lane+1)
        u64 a0 = 0ull, a1 = 0ull;
        for (int j = 0; j < Tt - 1; j += 2) {
            float2 p0 = *(const float2*)&P0[j];
            float2 p1 = *(const float2*)&P1[j];
            u64 v0 = *(const u64*)&Vs[j * SROW + lane * 2];
            u64 v1 = *(const u64*)&Vs[(j + 1) * SROW + lane * 2];
            ffma2(a0, pk2(p0.x, p0.x), v0);
            ffma2(a0, pk2(p0.y, p0.y), v1);
            ffma2(a1, pk2(p1.x, p1.x), v0);
            ffma2(a1, pk2(p1.y, p1.y), v1);
        }
        {   // tail j = 196
            int j = Tt - 1;
            u64 v0 = *(const u64*)&Vs[j * SROW + lane * 2];
            ffma2(a0, pk2(P0[j], P0[j]), v0);
            ffma2(a1, pk2(P1[j], P1[j]), v0);
        }

        float2 o0 = upk2(a0), o1 = upk2(a1);
        o0.x *= inv0; o0.y *= inv0;
        o1.x *= inv1; o1.y *= inv1;
        *(float2*)&ctx[((size_t)(b * Tt + r0)) * Dd + h * DKk + lane * 2] = o0;
        *(float2*)&ctx[((size_t)(b * Tt + r1)) * Dd + h * DKk + lane * 2] = o1;
        __syncwarp();
    }
}

// ---------------------------------------------------------------------------
extern "C" void kernel_launch(void* const* d_in, const int* in_sizes, int n_in,
                              void* d_out, int out_size)
{
    const float* x  = (const float*)d_in[0];
    const float* Wq = (const float*)d_in[1];
    const float* bq = (const float*)d_in[2];
    const float* Wk = (const float*)d_in[3];
    const float* bk = (const float*)d_in[4];
    const float* Wv = (const float*)d_in[5];
    const float* bv = (const float*)d_in[6];
    const float* Wo = (const float*)d_in[7];
    const float* bo = (const float*)d_in[8];
    float* out = (float*)d_out;

    float *q, *k, *v, *ctx;
    cudaGetSymbolAddress((void**)&q,   g_q);
    cudaGetSymbolAddress((void**)&k,   g_k);
    cudaGetSymbolAddress((void**)&v,   g_v);
    cudaGetSymbolAddress((void**)&ctx, g_ctx);

    cudaFuncSetAttribute(attn2_kernel,
                         cudaFuncAttributeMaxDynamicSharedMemorySize, ATTN_SMEM);

    dim3 gridG(Dd / 128, (Mrows + 127) / 128);   // 6 x 99
    sgemm2_kernel<<<gridG, 256>>>(x, Wq, bq, q, 0);
    sgemm2_kernel<<<gridG, 256>>>(x, Wk, bk, k, 0);
    sgemm2_kernel<<<gridG, 256>>>(x, Wv, bv, v, 0);

    attn2_kernel<<<Bc * Hh, 512, ATTN_SMEM>>>(q, k, v, ctx);

    sgemm2_kernel<<<gridG, 256>>>(ctx, Wo, bo, out, 1);
}